// round 1
// baseline (speedup 1.0000x reference)
#include <cuda_runtime.h>
#include <stdint.h>

#define NTHREADS 512
#define NN 32768
#define NBINS 4096
#define PRE_NMS_K 300
#define POST_KK 100
#define CAND_CAP 4096
#define MW 5  /* ceil(300/64) */

/* ---- shared memory layout (bytes) ---- */
#define KEYS_OFF   0
#define HIST_OFF   (KEYS_OFF + NN * 4)            /* 131072 */
#define CSUM_OFF   (HIST_OFF + NBINS * 4)         /* 147456 */
#define CPRE_OFF   (CSUM_OFF + NTHREADS * 4)      /* 149504 */
#define CAND_OFF   (CPRE_OFF + NTHREADS * 4)      /* 151552 (8B aligned) */
#define BX1_OFF    (CAND_OFF + CAND_CAP * 8)      /* 184320 */
#define BY1_OFF    (BX1_OFF + PRE_NMS_K * 4)
#define BX2_OFF    (BY1_OFF + PRE_NMS_K * 4)
#define BY2_OFF    (BX2_OFF + PRE_NMS_K * 4)
#define BAREA_OFF  (BY2_OFF + PRE_NMS_K * 4)
#define MASK_OFF   (BAREA_OFF + PRE_NMS_K * 4)    /* 190320 (8B aligned) */
#define KEEP_OFF   (MASK_OFF + PRE_NMS_K * MW * 8)/* 202320 */
#define SCAL_OFF   (KEEP_OFF + MW * 8)            /* 202360 */
#define SMEM_BYTES (SCAL_OFF + 16)                /* 202376 */

__global__ void __launch_bounds__(NTHREADS, 1)
proposal_kernel(const float* __restrict__ cls_prob,
                const float* __restrict__ boxes,
                const float* __restrict__ deltas,
                const float* __restrict__ im_info,
                float* __restrict__ out)
{
    extern __shared__ unsigned char smem[];
    uint32_t*           keys  = (uint32_t*)(smem + KEYS_OFF);
    int*                hist  = (int*)(smem + HIST_OFF);
    int*                csum  = (int*)(smem + CSUM_OFF);
    int*                cpre  = (int*)(smem + CPRE_OFF);
    unsigned long long* cand  = (unsigned long long*)(smem + CAND_OFF);
    float*              bx1   = (float*)(smem + BX1_OFF);
    float*              by1   = (float*)(smem + BY1_OFF);
    float*              bx2   = (float*)(smem + BX2_OFF);
    float*              by2   = (float*)(smem + BY2_OFF);
    float*              barea = (float*)(smem + BAREA_OFF);
    unsigned long long* maskA = (unsigned long long*)(smem + MASK_OFF);
    unsigned long long* keepw = (unsigned long long*)(smem + KEEP_OFF);
    int*                scal  = (int*)(smem + SCAL_OFF); /* [0]=cand cnt, [1]=bstar */

    const int b   = blockIdx.x;
    const int tid = threadIdx.x;

    for (int i = tid; i < NBINS; i += NTHREADS) hist[i] = 0;
    if (tid == 0) { scal[0] = 0; scal[1] = NBINS; }
    __syncthreads();

    /* ---- Phase A: load scores, key cache + histogram ---- */
    const float2* cp = (const float2*)(cls_prob + (size_t)b * (NN * 2));
#pragma unroll 4
    for (int k = 0; k < NN / NTHREADS; k++) {
        int j = tid + k * NTHREADS;
        float s = cp[j].y;                 /* cls_prob[b, j, 1] */
        uint32_t key = 0u;
        if (s >= 0.05f) {                  /* SCORE_THRESH; invalid -> key 0 */
            key = __float_as_uint(s);      /* s>0 => bits monotone in s */
            int bin = (int)(s * 4096.0f);
            bin = bin < NBINS - 1 ? bin : NBINS - 1;
            atomicAdd(&hist[bin], 1);
        }
        keys[j] = key;
    }
    __syncthreads();

    /* ---- Chunk sums from TOP + block inclusive scan ---- */
    {
        int base = NBINS - 8 * (tid + 1);
        int s8 = 0;
#pragma unroll
        for (int u = 0; u < 8; u++) s8 += hist[base + u];
        csum[tid] = s8;
        cpre[tid] = s8;
    }
    __syncthreads();
    for (int off = 1; off < NTHREADS; off <<= 1) {
        int t = (tid >= off) ? cpre[tid - off] : 0;
        __syncthreads();
        cpre[tid] += t;
        __syncthreads();
    }
    int total  = cpre[NTHREADS - 1];
    int target = total < PRE_NMS_K ? total : PRE_NMS_K;
    {
        int inc = cpre[tid];
        int exc = inc - csum[tid];
        if (target > 0 && exc < target && target <= inc) {
            int base = NBINS - 8 * (tid + 1);
            int cum = exc;
            int bsel = base;
            for (int u = 7; u >= 0; u--) {
                cum += hist[base + u];
                if (cum >= target) { bsel = base + u; break; }
            }
            scal[1] = bsel;
        }
    }
    __syncthreads();
    int bstar = scal[1];

    /* ---- Phase B: collect candidates with bin >= bstar ---- */
#pragma unroll 4
    for (int k = 0; k < NN / NTHREADS; k++) {
        int j = tid + k * NTHREADS;
        uint32_t key = keys[j];
        if (key != 0u) {
            float s = __uint_as_float(key);
            int bin = (int)(s * 4096.0f);
            bin = bin < NBINS - 1 ? bin : NBINS - 1;
            if (bin >= bstar) {
                int p = atomicAdd(&scal[0], 1);
                if (p < CAND_CAP)
                    cand[p] = ((unsigned long long)key << 32) |
                              (unsigned long long)(0xFFFFFFFFu - (uint32_t)j);
            }
        }
    }
    __syncthreads();
    int cnt = scal[0] < CAND_CAP ? scal[0] : CAND_CAP;
    int M = 512;
    while (M < cnt) M <<= 1;
    for (int i = cnt + tid; i < M; i += NTHREADS) cand[i] = 0ull;
    __syncthreads();

    /* ---- Bitonic sort descending: (score desc, idx asc) == jax top_k order ---- */
    for (int k2 = 2; k2 <= M; k2 <<= 1) {
        for (int jj = k2 >> 1; jj > 0; jj >>= 1) {
            for (int i = tid; i < M; i += NTHREADS) {
                int l = i ^ jj;
                if (l > i) {
                    unsigned long long a = cand[i];
                    unsigned long long c = cand[l];
                    bool up = ((i & k2) == 0);
                    if (up ? (a < c) : (a > c)) { cand[i] = c; cand[l] = a; }
                }
            }
            __syncthreads();
        }
    }

    int L = cnt < PRE_NMS_K ? cnt : PRE_NMS_K;

    /* ---- Decode + clip the selected boxes (rn intrinsics: no FMA contraction) ---- */
    if (tid < L) {
        unsigned long long kk = cand[tid];
        int j = (int)(0xFFFFFFFFu - (uint32_t)(kk & 0xFFFFFFFFull));
        float4 bb = *(const float4*)(boxes  + ((size_t)b * NN + j) * 4);
        float4 dd = *(const float4*)(deltas + ((size_t)b * NN + j) * 4);
        float w  = __fadd_rn(__fsub_rn(bb.z, bb.x), 1.0f);
        float h  = __fadd_rn(__fsub_rn(bb.w, bb.y), 1.0f);
        float cx = __fadd_rn(bb.x, __fmul_rn(0.5f, w));
        float cy = __fadd_rn(bb.y, __fmul_rn(0.5f, h));
        float d0 = __fmul_rn(dd.x, 0.1f);
        float d1 = __fmul_rn(dd.y, 0.1f);
        float d2 = __fmul_rn(dd.z, 0.2f);
        float d3 = __fmul_rn(dd.w, 0.2f);
        float pcx = __fadd_rn(__fmul_rn(d0, w), cx);
        float pcy = __fadd_rn(__fmul_rn(d1, h), cy);
        float pw  = __fmul_rn((float)exp((double)d2), w);
        float ph  = __fmul_rn((float)exp((double)d3), h);
        float x1 = __fsub_rn(pcx, __fmul_rn(0.5f, pw));
        float y1 = __fsub_rn(pcy, __fmul_rn(0.5f, ph));
        float x2 = __fadd_rn(pcx, __fmul_rn(0.5f, pw));
        float y2 = __fadd_rn(pcy, __fmul_rn(0.5f, ph));
        float hmax = __fsub_rn(im_info[b * 3 + 0], 1.0f);
        float wmax = __fsub_rn(im_info[b * 3 + 1], 1.0f);
        x1 = fminf(fmaxf(x1, 0.0f), wmax);
        y1 = fminf(fmaxf(y1, 0.0f), hmax);
        x2 = fminf(fmaxf(x2, 0.0f), wmax);
        y2 = fminf(fmaxf(y2, 0.0f), hmax);
        bx1[tid] = x1; by1[tid] = y1; bx2[tid] = x2; by2[tid] = y2;
        barea[tid] = __fmul_rn(__fadd_rn(__fsub_rn(x2, x1), 1.0f),
                               __fadd_rn(__fsub_rn(y2, y1), 1.0f));
    }
    __syncthreads();

    /* ---- IoU suppression bitmasks: mask[i] has bit j set iff j>i && iou>0.3 ---- */
    for (int item = tid; item < PRE_NMS_K * MW; item += NTHREADS) {
        int i = item / MW, w = item % MW;
        unsigned long long bits = 0ull;
        if (i < L) {
            float xi1 = bx1[i], yi1 = by1[i], xi2 = bx2[i], yi2 = by2[i], ai = barea[i];
            int j0 = w * 64;
            int jend = (j0 + 64 < L) ? j0 + 64 : L;
            for (int j = (j0 > i + 1 ? j0 : i + 1); j < jend; j++) {
                float xx1 = fmaxf(xi1, bx1[j]);
                float yy1 = fmaxf(yi1, by1[j]);
                float xx2 = fminf(xi2, bx2[j]);
                float yy2 = fminf(yi2, by2[j]);
                float iw = fmaxf(__fadd_rn(__fsub_rn(xx2, xx1), 1.0f), 0.0f);
                float ih = fmaxf(__fadd_rn(__fsub_rn(yy2, yy1), 1.0f), 0.0f);
                float inter = __fmul_rn(iw, ih);
                float uni = __fsub_rn(__fadd_rn(ai, barea[j]), inter);
                float iou = __fdiv_rn(inter, uni);
                if (iou > 0.3f) bits |= 1ull << (j - j0);
            }
        }
        maskA[item] = bits;
    }
    __syncthreads();

    /* ---- Serial greedy NMS over bitmasks (thread 0) ---- */
    if (tid == 0) {
        unsigned long long r0 = 0, r1 = 0, r2 = 0, r3 = 0, r4 = 0;
        for (int i = 0; i < L; i++) {
            int w = i >> 6, bp = i & 63;
            unsigned long long rw = (w == 0) ? r0 : (w == 1) ? r1 : (w == 2) ? r2
                                  : (w == 3) ? r3 : r4;
            if (!((rw >> bp) & 1ull)) {
                const unsigned long long* m = maskA + i * MW;
                r0 |= m[0]; r1 |= m[1]; r2 |= m[2]; r3 |= m[3]; r4 |= m[4];
            }
        }
#pragma unroll
        for (int w = 0; w < MW; w++) {
            int lo = w * 64;
            unsigned long long vm;
            if (L <= lo) vm = 0ull;
            else if (L - lo >= 64) vm = ~0ull;
            else vm = (1ull << (L - lo)) - 1ull;
            unsigned long long rw = (w == 0) ? r0 : (w == 1) ? r1 : (w == 2) ? r2
                                  : (w == 3) ? r3 : r4;
            keepw[w] = (~rw) & vm;
        }
    }
    __syncthreads();

    /* ---- Output: zero then scatter kept rows by rank ---- */
    float* outb = out + (size_t)b * (POST_KK * 5);
    for (int t = tid; t < POST_KK * 5; t += NTHREADS) outb[t] = 0.0f;
    __syncthreads();
    if (tid < L) {
        int w = tid >> 6, bp = tid & 63;
        if ((keepw[w] >> bp) & 1ull) {
            int rank = 0;
            for (int u = 0; u < w; u++) rank += __popcll(keepw[u]);
            rank += __popcll(keepw[w] & ((1ull << bp) - 1ull));
            if (rank < POST_KK) {
                float* row = outb + rank * 5;
                row[0] = (float)b;
                row[1] = bx1[tid];
                row[2] = by1[tid];
                row[3] = bx2[tid];
                row[4] = by2[tid];
            }
        }
    }
}

extern "C" void kernel_launch(void* const* d_in, const int* in_sizes, int n_in,
                              void* d_out, int out_size) {
    const float* cls_prob = (const float*)d_in[0];
    const float* boxes    = (const float*)d_in[1];
    const float* deltas   = (const float*)d_in[2];
    const float* im_info  = (const float*)d_in[3];
    int B = in_sizes[3] / 3;   /* im_info is (B,3) */
    cudaFuncSetAttribute(proposal_kernel,
                         cudaFuncAttributeMaxDynamicSharedMemorySize, SMEM_BYTES);
    proposal_kernel<<<B, NTHREADS, SMEM_BYTES>>>(cls_prob, boxes, deltas,
                                                 im_info, (float*)d_out);
}

// round 5
// speedup vs baseline: 1.0304x; 1.0304x over previous
#include <cuda_runtime.h>
#include <stdint.h>

#define NTHREADS 512
#define NN 32768
#define NBINS 4096
#define PRE_NMS_K 300
#define POST_KK 100
#define CAND_CAP 4096
#define MW 5  /* ceil(300/64) */

/* ---- shared memory layout (bytes) ---- */
#define KEYS_OFF   0
#define HIST_OFF   (KEYS_OFF + NN * 4)             /* 131072 */
#define CAND_OFF   (HIST_OFF + NBINS * 4)          /* 147456, 8B aligned */
#define BX1_OFF    (CAND_OFF + CAND_CAP * 8)       /* 180224 */
#define BY1_OFF    (BX1_OFF + PRE_NMS_K * 4)
#define BX2_OFF    (BY1_OFF + PRE_NMS_K * 4)
#define BY2_OFF    (BX2_OFF + PRE_NMS_K * 4)
#define BAREA_OFF  (BY2_OFF + PRE_NMS_K * 4)
#define MASK_OFF   (BAREA_OFF + PRE_NMS_K * 4)     /* 186224, 8B aligned */
#define KEEP_OFF   (MASK_OFF + PRE_NMS_K * MW * 8) /* 198224 */
#define WS_OFF     (KEEP_OFF + MW * 8)             /* 198264 -> pad to 8 */
#define SCAL_OFF   (WS_OFF + 16 * 4)
#define SCALF_OFF  (SCAL_OFF + 8 * 4)
#define SMEM_BYTES (SCALF_OFF + 8 * 4)

__global__ void __launch_bounds__(NTHREADS, 1)
proposal_kernel(const float* __restrict__ cls_prob,
                const float* __restrict__ boxes,
                const float* __restrict__ deltas,
                const float* __restrict__ im_info,
                float* __restrict__ out)
{
    extern __shared__ unsigned char smem[];
    uint32_t*           keys  = (uint32_t*)(smem + KEYS_OFF);
    int*                hist  = (int*)(smem + HIST_OFF);
    unsigned long long* cand  = (unsigned long long*)(smem + CAND_OFF);
    float*              bx1   = (float*)(smem + BX1_OFF);
    float*              by1   = (float*)(smem + BY1_OFF);
    float*              bx2   = (float*)(smem + BX2_OFF);
    float*              by2   = (float*)(smem + BY2_OFF);
    float*              barea = (float*)(smem + BAREA_OFF);
    unsigned long long* maskA = (unsigned long long*)(smem + MASK_OFF);
    unsigned long long* keepw = (unsigned long long*)(smem + KEEP_OFF);
    int*                wsums = (int*)(smem + WS_OFF);
    int*                scal  = (int*)(smem + SCAL_OFF);  /* 0=cnt 1=bstar 2=c09 3=c005 */
    float*              scalf = (float*)(smem + SCALF_OFF);/* 0=base 1=scale */

    const int b    = blockIdx.x;
    const int tid  = threadIdx.x;
    const int lane = tid & 31;
    const int wrp  = tid >> 5;

    for (int i = tid; i < NBINS; i += NTHREADS) hist[i] = 0;
    if (tid == 0) { scal[0] = 0; scal[1] = NBINS; scal[2] = 0; scal[3] = 0; }
    __syncthreads();

    /* ---- Phase A: load scores (float4 = 2 items), cache keys, ballot counts,
            speculative fine histogram over [0.9, 1.0] ---- */
    const float4* cp4 = (const float4*)(cls_prob + (size_t)b * (NN * 2));
    int c09 = 0, c005 = 0;
#pragma unroll 8
    for (int k = 0; k < (NN / 2) / NTHREADS; k++) {
        int m = tid + k * NTHREADS;
        float4 v = cp4[m];
        float s0 = v.y, s1 = v.w;             /* cls_prob[b, 2m, 1], [b, 2m+1, 1] */
        uint32_t k0 = (s0 >= 0.05f) ? __float_as_uint(s0) : 0u;
        uint32_t k1 = (s1 >= 0.05f) ? __float_as_uint(s1) : 0u;
        *(uint2*)&keys[2 * m] = make_uint2(k0, k1);
        unsigned b9a = __ballot_sync(0xFFFFFFFFu, s0 >= 0.9f);
        unsigned b9b = __ballot_sync(0xFFFFFFFFu, s1 >= 0.9f);
        unsigned b5a = __ballot_sync(0xFFFFFFFFu, k0 != 0u);
        unsigned b5b = __ballot_sync(0xFFFFFFFFu, k1 != 0u);
        c09  += __popc(b9a) + __popc(b9b);
        c005 += __popc(b5a) + __popc(b5b);
        if (s0 >= 0.9f) {
            int bin = (int)((s0 - 0.9f) * 40960.0f);
            atomicAdd(&hist[bin < NBINS - 1 ? bin : NBINS - 1], 1);
        }
        if (s1 >= 0.9f) {
            int bin = (int)((s1 - 0.9f) * 40960.0f);
            atomicAdd(&hist[bin < NBINS - 1 ? bin : NBINS - 1], 1);
        }
    }
    if (lane == 0) { atomicAdd(&scal[2], c09); atomicAdd(&scal[3], c005); }
    __syncthreads();

    int cnt09 = scal[2], cnt005 = scal[3];
    int target0 = cnt005 < PRE_NMS_K ? cnt005 : PRE_NMS_K;
    bool fast = (cnt09 >= target0);
    if (tid == 0) {
        scalf[0] = fast ? 0.9f : 0.05f;
        scalf[1] = fast ? 40960.0f : (4096.0f / 0.95f);
    }
    if (!fast) {
        /* fallback: rebuild histogram over [0.05, 1.0] from cached keys */
        __syncthreads();
        for (int i = tid; i < NBINS; i += NTHREADS) hist[i] = 0;
        __syncthreads();
        for (int k = 0; k < (NN / 2) / NTHREADS; k++) {
            int m = tid + k * NTHREADS;
            uint2 kk = *(uint2*)&keys[2 * m];
            if (kk.x) {
                float s = __uint_as_float(kk.x);
                int bin = (int)((s - 0.05f) * (4096.0f / 0.95f));
                atomicAdd(&hist[bin < NBINS - 1 ? bin : NBINS - 1], 1);
            }
            if (kk.y) {
                float s = __uint_as_float(kk.y);
                int bin = (int)((s - 0.05f) * (4096.0f / 0.95f));
                atomicAdd(&hist[bin < NBINS - 1 ? bin : NBINS - 1], 1);
            }
        }
    }
    __syncthreads();
    float tbase = scalf[0], tscale = scalf[1];

    /* ---- chunk sums (top-down) + shfl block scan -> bstar bin ---- */
    int base8 = NBINS - 8 * (tid + 1);
    int4 h0 = *(int4*)&hist[base8];
    int4 h1 = *(int4*)&hist[base8 + 4];
    int s8 = h0.x + h0.y + h0.z + h0.w + h1.x + h1.y + h1.z + h1.w;
    int v = s8;
#pragma unroll
    for (int off = 1; off < 32; off <<= 1) {
        int n = __shfl_up_sync(0xFFFFFFFFu, v, off);
        if (lane >= off) v += n;
    }
    if (lane == 31) wsums[wrp] = v;
    __syncthreads();
    if (wrp == 0) {
        int t = (lane < 16) ? wsums[lane] : 0;
#pragma unroll
        for (int off = 1; off < 16; off <<= 1) {
            int n = __shfl_up_sync(0xFFFFFFFFu, t, off);
            if (lane >= off) t += n;
        }
        if (lane < 16) wsums[lane] = t;
    }
    __syncthreads();
    int inc = v + (wrp > 0 ? wsums[wrp - 1] : 0);
    int total = wsums[15];
    int target = total < PRE_NMS_K ? total : PRE_NMS_K;
    {
        int exc = inc - s8;
        if (target > 0 && exc < target && target <= inc) {
            int cum = exc, bsel = base8;
            for (int u = 7; u >= 0; u--) {
                cum += hist[base8 + u];
                if (cum >= target) { bsel = base8 + u; break; }
            }
            scal[1] = bsel;
        }
    }
    __syncthreads();
    int bstar = scal[1];

    /* ---- Phase B: collect candidates with bin >= bstar ---- */
    for (int k = 0; k < (NN / 2) / NTHREADS; k++) {
        int m = tid + k * NTHREADS;
        uint2 kk = *(uint2*)&keys[2 * m];
#pragma unroll
        for (int h = 0; h < 2; h++) {
            uint32_t key = h ? kk.y : kk.x;
            int j = 2 * m + h;
            if (key) {
                float s = __uint_as_float(key);
                if (s >= tbase) {
                    int bin = (int)((s - tbase) * tscale);
                    bin = bin < NBINS - 1 ? bin : NBINS - 1;
                    if (bin >= bstar) {
                        int p = atomicAdd(&scal[0], 1);
                        if (p < CAND_CAP)
                            cand[p] = ((unsigned long long)key << 32) |
                                      (unsigned long long)(0xFFFFFFFFu - (uint32_t)j);
                    }
                }
            }
        }
    }
    __syncthreads();
    int cnt = scal[0] < CAND_CAP ? scal[0] : CAND_CAP;
    int M = 512;
    while (M < cnt) M <<= 1;
    for (int i = cnt + tid; i < M; i += NTHREADS) cand[i] = 0ull;
    __syncthreads();

    /* ---- Bitonic sort descending: (score desc, idx asc) == jax top_k order ---- */
    if (M == 512) {
        /* hybrid: one element per thread; jj<=16 in registers via shfl */
        unsigned long long a = cand[tid];
#pragma unroll
        for (int k2 = 2; k2 <= 32; k2 <<= 1) {
#pragma unroll
            for (int jj = 16; jj >= 1; jj >>= 1) {
                if (jj <= (k2 >> 1)) {
                    unsigned long long c = __shfl_xor_sync(0xFFFFFFFFu, a, jj);
                    bool keepmax = (((tid & k2) == 0) == ((tid & jj) == 0));
                    unsigned long long mx = a > c ? a : c;
                    unsigned long long mn = a > c ? c : a;
                    a = keepmax ? mx : mn;
                }
            }
        }
        cand[tid] = a;
        __syncthreads();
        for (int k2 = 64; k2 <= 512; k2 <<= 1) {
            for (int jj = k2 >> 1; jj >= 32; jj >>= 1) {
                int l = tid ^ jj;
                if (l > tid) {
                    unsigned long long x = cand[tid];
                    unsigned long long y = cand[l];
                    bool up = ((tid & k2) == 0);
                    if (up ? (x < y) : (x > y)) { cand[tid] = y; cand[l] = x; }
                }
                __syncthreads();
            }
            a = cand[tid];
#pragma unroll
            for (int jj = 16; jj >= 1; jj >>= 1) {
                unsigned long long c = __shfl_xor_sync(0xFFFFFFFFu, a, jj);
                bool keepmax = (((tid & k2) == 0) == ((tid & jj) == 0));
                unsigned long long mx = a > c ? a : c;
                unsigned long long mn = a > c ? c : a;
                a = keepmax ? mx : mn;
            }
            cand[tid] = a;
            __syncthreads();
        }
    } else {
        for (int k2 = 2; k2 <= M; k2 <<= 1) {
            for (int jj = k2 >> 1; jj > 0; jj >>= 1) {
                for (int i = tid; i < M; i += NTHREADS) {
                    int l = i ^ jj;
                    if (l > i) {
                        unsigned long long a = cand[i];
                        unsigned long long c = cand[l];
                        bool up = ((i & k2) == 0);
                        if (up ? (a < c) : (a > c)) { cand[i] = c; cand[l] = a; }
                    }
                }
                __syncthreads();
            }
        }
    }

    int L = cnt < PRE_NMS_K ? cnt : PRE_NMS_K;

    /* ---- Decode + clip selected boxes (rn intrinsics: no FMA contraction) ---- */
    if (tid < L) {
        unsigned long long kk = cand[tid];
        int j = (int)(0xFFFFFFFFu - (uint32_t)(kk & 0xFFFFFFFFull));
        float4 bb = *(const float4*)(boxes  + ((size_t)b * NN + j) * 4);
        float4 dd = *(const float4*)(deltas + ((size_t)b * NN + j) * 4);
        float w  = __fadd_rn(__fsub_rn(bb.z, bb.x), 1.0f);
        float h  = __fadd_rn(__fsub_rn(bb.w, bb.y), 1.0f);
        float cx = __fadd_rn(bb.x, __fmul_rn(0.5f, w));
        float cy = __fadd_rn(bb.y, __fmul_rn(0.5f, h));
        float d0 = __fmul_rn(dd.x, 0.1f);
        float d1 = __fmul_rn(dd.y, 0.1f);
        float d2 = __fmul_rn(dd.z, 0.2f);
        float d3 = __fmul_rn(dd.w, 0.2f);
        float pcx = __fadd_rn(__fmul_rn(d0, w), cx);
        float pcy = __fadd_rn(__fmul_rn(d1, h), cy);
        float pw  = __fmul_rn((float)exp((double)d2), w);
        float ph  = __fmul_rn((float)exp((double)d3), h);
        float x1 = __fsub_rn(pcx, __fmul_rn(0.5f, pw));
        float y1 = __fsub_rn(pcy, __fmul_rn(0.5f, ph));
        float x2 = __fadd_rn(pcx, __fmul_rn(0.5f, pw));
        float y2 = __fadd_rn(pcy, __fmul_rn(0.5f, ph));
        float hmax = __fsub_rn(im_info[b * 3 + 0], 1.0f);
        float wmax = __fsub_rn(im_info[b * 3 + 1], 1.0f);
        x1 = fminf(fmaxf(x1, 0.0f), wmax);
        y1 = fminf(fmaxf(y1, 0.0f), hmax);
        x2 = fminf(fmaxf(x2, 0.0f), wmax);
        y2 = fminf(fmaxf(y2, 0.0f), hmax);
        bx1[tid] = x1; by1[tid] = y1; bx2[tid] = x2; by2[tid] = y2;
        barea[tid] = __fmul_rn(__fadd_rn(__fsub_rn(x2, x1), 1.0f),
                               __fadd_rn(__fsub_rn(y2, y1), 1.0f));
    }
    __syncthreads();

    /* ---- IoU suppression bitmasks: mask[i] bit j set iff j>i && iou>0.3 ---- */
    for (int item = tid; item < PRE_NMS_K * MW; item += NTHREADS) {
        int i = item / MW, w = item % MW;
        unsigned long long bits = 0ull;
        if (i < L) {
            float xi1 = bx1[i], yi1 = by1[i], xi2 = bx2[i], yi2 = by2[i], ai = barea[i];
            int j0 = w * 64;
            int jend = (j0 + 64 < L) ? j0 + 64 : L;
            for (int j = (j0 > i + 1 ? j0 : i + 1); j < jend; j++) {
                float xx1 = fmaxf(xi1, bx1[j]);
                float yy1 = fmaxf(yi1, by1[j]);
                float xx2 = fminf(xi2, bx2[j]);
                float yy2 = fminf(yi2, by2[j]);
                float iw = fmaxf(__fadd_rn(__fsub_rn(xx2, xx1), 1.0f), 0.0f);
                float ih = fmaxf(__fadd_rn(__fsub_rn(yy2, yy1), 1.0f), 0.0f);
                float inter = __fmul_rn(iw, ih);
                float uni = __fsub_rn(__fadd_rn(ai, barea[j]), inter);
                float iou = __fdiv_rn(inter, uni);
                if (iou > 0.3f) bits |= 1ull << (j - j0);
            }
        }
        maskA[item] = bits;
    }
    __syncthreads();

    /* ---- Serial greedy NMS, chunked to keep LDS out of the decision chain ---- */
    if (tid == 0) {
        unsigned long long r[MW] = {0ull, 0ull, 0ull, 0ull, 0ull};
#pragma unroll
        for (int w = 0; w < MW; w++) {
            int i0w = w * 64;
            if (i0w < L) {
                int iend = (i0w + 64 < L) ? i0w + 64 : L;
                for (int c0 = i0w; c0 < iend; c0 += 16) {
                    int ce = (c0 + 16 < iend) ? c0 + 16 : iend;
                    unsigned long long mm[16];
#pragma unroll
                    for (int t = 0; t < 16; t++)
                        mm[t] = (c0 + t < ce) ? maskA[(c0 + t) * MW + w] : 0ull;
#pragma unroll
                    for (int t = 0; t < 16; t++) {
                        int i = c0 + t;
                        if (i < ce && !((r[w] >> (i - i0w)) & 1ull))
                            r[w] |= mm[t];
                    }
                }
                /* deferred: fold kept items' later-word masks */
                int nb = iend - i0w;
                unsigned long long vm = (nb >= 64) ? ~0ull : ((1ull << nb) - 1ull);
                unsigned long long kw = (~r[w]) & vm;
                while (kw) {
                    int t = __ffsll((long long)kw) - 1;
                    kw &= kw - 1ull;
                    const unsigned long long* m = maskA + (i0w + t) * MW;
#pragma unroll
                    for (int w2 = 0; w2 < MW; w2++)
                        if (w2 > w) r[w2] |= m[w2];
                }
            }
        }
#pragma unroll
        for (int w = 0; w < MW; w++) {
            int lo = w * 64;
            unsigned long long vm = (L <= lo) ? 0ull
                                  : ((L - lo >= 64) ? ~0ull : ((1ull << (L - lo)) - 1ull));
            keepw[w] = (~r[w]) & vm;
        }
    }
    __syncthreads();

    /* ---- Output: zero then scatter kept rows by rank ---- */
    float* outb = out + (size_t)b * (POST_KK * 5);
    for (int t = tid; t < POST_KK * 5; t += NTHREADS) outb[t] = 0.0f;
    __syncthreads();
    if (tid < L) {
        int w = tid >> 6, bp = tid & 63;
        if ((keepw[w] >> bp) & 1ull) {
            int rank = 0;
            for (int u = 0; u < w; u++) rank += __popcll(keepw[u]);
            rank += __popcll(keepw[w] & ((1ull << bp) - 1ull));
            if (rank < POST_KK) {
                float* row = outb + rank * 5;
                row[0] = (float)b;
                row[1] = bx1[tid];
                row[2] = by1[tid];
                row[3] = bx2[tid];
                row[4] = by2[tid];
            }
        }
    }
}

extern "C" void kernel_launch(void* const* d_in, const int* in_sizes, int n_in,
                              void* d_out, int out_size) {
    const float* cls_prob = (const float*)d_in[0];
    const float* boxes    = (const float*)d_in[1];
    const float* deltas   = (const float*)d_in[2];
    const float* im_info  = (const float*)d_in[3];
    int B = in_sizes[3] / 3;   /* im_info is (B,3) */
    cudaFuncSetAttribute(proposal_kernel,
                         cudaFuncAttributeMaxDynamicSharedMemorySize, SMEM_BYTES);
    proposal_kernel<<<B, NTHREADS, SMEM_BYTES>>>(cls_prob, boxes, deltas,
                                                 im_info, (float*)d_out);
}